// round 2
// baseline (speedup 1.0000x reference)
#include <cuda_runtime.h>
#include <cstdint>

// Problem constants (fixed shapes from reference):
// enc_state: (4,256,512)  dec_state: (4,64,512)
// W1: (512,1024)  b1: (512)  W2: (1000,512)  b2: (1000)
// out: (4,256,64,1000) fp32
#define B_DIM 4
#define T_DIM 256
#define U_DIM 64
#define D_DIM 512
#define K_DIM 512
#define V_DIM 1000
#define M_TOTAL (B_DIM * T_DIM * U_DIM)   // 65536

// Scratch for projections (allocation-free: __device__ globals)
__device__ float g_He[B_DIM * T_DIM * K_DIM];   // 1024 x 512
__device__ float g_Hd[B_DIM * U_DIM * K_DIM];   // 256 x 512  (includes +b1)

// ---------------------------------------------------------------------------
// Projection kernel: C[m][n] = sum_d X[m][d] * W1[n][dOff + d]  (+ b1[n])
// X: M x 512 row-major. W1: 512 x 1024 row-major. out: M x 512.
// BM=BN=64, BK=16, 256 threads, 4x4 per thread. fp32 exact.
// ---------------------------------------------------------------------------
__global__ __launch_bounds__(256)
void proj_kernel(const float* __restrict__ X,
                 const float* __restrict__ W1,
                 const float* __restrict__ b1,
                 float* __restrict__ out,
                 int dOff, int addBias)
{
    __shared__ float As[64][17];
    __shared__ float Bs[64][17];
    const int m0 = blockIdx.x * 64;
    const int n0 = blockIdx.y * 64;
    const int tid = threadIdx.x;
    const int tx = tid & 15;
    const int ty = tid >> 4;

    float acc[4][4];
#pragma unroll
    for (int i = 0; i < 4; i++)
#pragma unroll
        for (int j = 0; j < 4; j++) acc[i][j] = 0.0f;

    for (int k0 = 0; k0 < D_DIM; k0 += 16) {
#pragma unroll
        for (int i = 0; i < 4; i++) {
            int e = tid + i * 256;
            int r = e >> 4;
            int d = e & 15;
            As[r][d] = X[(m0 + r) * D_DIM + k0 + d];
            Bs[r][d] = W1[(n0 + r) * (2 * D_DIM) + dOff + k0 + d];
        }
        __syncthreads();
#pragma unroll
        for (int d = 0; d < 16; d++) {
            float a[4], b[4];
#pragma unroll
            for (int i = 0; i < 4; i++) a[i] = As[ty * 4 + i][d];
#pragma unroll
            for (int j = 0; j < 4; j++) b[j] = Bs[tx * 4 + j][d];
#pragma unroll
            for (int i = 0; i < 4; i++)
#pragma unroll
                for (int j = 0; j < 4; j++) acc[i][j] += a[i] * b[j];
        }
        __syncthreads();
    }

#pragma unroll
    for (int i = 0; i < 4; i++) {
#pragma unroll
        for (int j = 0; j < 4; j++) {
            int n = n0 + tx * 4 + j;
            float v = acc[i][j];
            if (addBias) v += b1[n];
            out[(m0 + ty * 4 + i) * K_DIM + n] = v;
        }
    }
}

// ---------------------------------------------------------------------------
// Joint kernel: out[r][v] = sum_k tanh(He[bt][k] + Hd[bu][k]) * W2[v][k] + b2[v]
// r = ((b*T + t)*U + u), M=65536, N=1000, K=512.
// BM=128, BN=64, BK=32, 8 warps (4 in M x 2 in N), warp tile 32x32.
// mma.sync.aligned.m16n8k8 tf32 with fp32 accumulation.
// ---------------------------------------------------------------------------
#define BM 128
#define BN 64
#define BK 32
#define KSTRIDE 36   // BK + 4 pad: (36*gp + tg) mod 32 covers all banks

__device__ __forceinline__ uint32_t f2tf32(float x) {
    uint32_t y;
    asm("cvt.rna.tf32.f32 %0, %1;" : "=r"(y) : "f"(x));
    return y;
}

__device__ __forceinline__ void mma_tf32(float* c,
                                         uint32_t a0, uint32_t a1, uint32_t a2, uint32_t a3,
                                         uint32_t b0, uint32_t b1)
{
    asm volatile(
        "mma.sync.aligned.m16n8k8.row.col.f32.tf32.tf32.f32 "
        "{%0,%1,%2,%3}, {%4,%5,%6,%7}, {%8,%9}, {%0,%1,%2,%3};\n"
        : "+f"(c[0]), "+f"(c[1]), "+f"(c[2]), "+f"(c[3])
        : "r"(a0), "r"(a1), "r"(a2), "r"(a3), "r"(b0), "r"(b1));
}

__global__ __launch_bounds__(256)
void joint_kernel(const float* __restrict__ He,
                  const float* __restrict__ Hd,
                  const float* __restrict__ W2,
                  const float* __restrict__ b2,
                  float* __restrict__ out)
{
    __shared__ uint32_t As[BM * KSTRIDE];
    __shared__ uint32_t Bs[BN * KSTRIDE];

    const int tid = threadIdx.x;
    const int warp = tid >> 5;
    const int lane = tid & 31;
    const int wm = warp & 3;          // 4 warps along M
    const int wn = warp >> 2;         // 2 warps along N
    const int mrow = wm * 32;
    const int ncol = wn * 32;
    const int gp = lane >> 2;         // group id 0..7
    const int tg = lane & 3;          // thread-in-group 0..3

    const int v0 = blockIdx.x * BN;
    const int mbase = blockIdx.y * BM;

    // A-fill mapping: each thread fills one half-row (16 k values)
    const int arow = tid >> 1;
    const int akoff = (tid & 1) * 16;
    {
        // compute per-thread source rows once
    }
    const int grow = mbase + arow;
    const int bidx = grow >> 14;               // / (T*U) = /16384
    const int rem = grow & 16383;
    const int t = rem >> 6;
    const int u = rem & 63;
    const float* heRow = He + (bidx * T_DIM + t) * K_DIM + akoff;
    const float* hdRow = Hd + (bidx * U_DIM + u) * K_DIM + akoff;

    // B-fill mapping: each thread fills 8 k values of one W2 row
    const int brow = tid >> 2;
    const int bkoff = (tid & 3) * 8;
    const int vrow = v0 + brow;
    const bool bvalid = (vrow < V_DIM);
    const float* w2Row = W2 + (bvalid ? vrow : 0) * K_DIM + bkoff;

    float acc[2][4][4];
#pragma unroll
    for (int mi = 0; mi < 2; mi++)
#pragma unroll
        for (int ni = 0; ni < 4; ni++)
#pragma unroll
            for (int q = 0; q < 4; q++) acc[mi][ni][q] = 0.0f;

    for (int k0 = 0; k0 < K_DIM; k0 += BK) {
        // Fill A tile: tanh(He + Hd) -> tf32
#pragma unroll
        for (int i = 0; i < 16; i++) {
            float h = tanhf(heRow[k0 + i] + hdRow[k0 + i]);
            As[arow * KSTRIDE + akoff + i] = f2tf32(h);
        }
        // Fill B tile: W2 -> tf32 (zeros past V)
        if (bvalid) {
#pragma unroll
            for (int i = 0; i < 8; i++)
                Bs[brow * KSTRIDE + bkoff + i] = f2tf32(w2Row[k0 + i]);
        } else {
#pragma unroll
            for (int i = 0; i < 8; i++)
                Bs[brow * KSTRIDE + bkoff + i] = 0u;
        }
        __syncthreads();

#pragma unroll
        for (int ks = 0; ks < 4; ks++) {
            const int kk = ks * 8;
            uint32_t bf[4][2];
#pragma unroll
            for (int ni = 0; ni < 4; ni++) {
                bf[ni][0] = Bs[(ncol + ni * 8 + gp) * KSTRIDE + kk + tg];
                bf[ni][1] = Bs[(ncol + ni * 8 + gp) * KSTRIDE + kk + tg + 4];
            }
#pragma unroll
            for (int mi = 0; mi < 2; mi++) {
                uint32_t a0 = As[(mrow + mi * 16 + gp) * KSTRIDE + kk + tg];
                uint32_t a1 = As[(mrow + mi * 16 + gp + 8) * KSTRIDE + kk + tg];
                uint32_t a2 = As[(mrow + mi * 16 + gp) * KSTRIDE + kk + tg + 4];
                uint32_t a3 = As[(mrow + mi * 16 + gp + 8) * KSTRIDE + kk + tg + 4];
#pragma unroll
                for (int ni = 0; ni < 4; ni++)
                    mma_tf32(acc[mi][ni], a0, a1, a2, a3, bf[ni][0], bf[ni][1]);
            }
        }
        __syncthreads();
    }

    // Epilogue: + b2, bounds check on V (cols come in even pairs; V=1000 even)
#pragma unroll
    for (int mi = 0; mi < 2; mi++) {
#pragma unroll
        for (int ni = 0; ni < 4; ni++) {
            int col = ncol + ni * 8 + tg * 2;
            int v = v0 + col;
            if (v < V_DIM) {
                int r0 = (mbase + mrow + mi * 16 + gp) * V_DIM;
                int r1 = r0 + 8 * V_DIM;
                float bb0 = b2[v];
                float bb1 = b2[v + 1];
                out[r0 + v]     = acc[mi][ni][0] + bb0;
                out[r0 + v + 1] = acc[mi][ni][1] + bb1;
                out[r1 + v]     = acc[mi][ni][2] + bb0;
                out[r1 + v + 1] = acc[mi][ni][3] + bb1;
            }
        }
    }
}

// ---------------------------------------------------------------------------
extern "C" void kernel_launch(void* const* d_in, const int* in_sizes, int n_in,
                              void* d_out, int out_size)
{
    const float* enc = (const float*)d_in[0];  // (4,256,512)
    const float* dec = (const float*)d_in[1];  // (4,64,512)
    const float* W1  = (const float*)d_in[2];  // (512,1024)
    const float* b1  = (const float*)d_in[3];  // (512)
    const float* W2  = (const float*)d_in[4];  // (1000,512)
    const float* b2  = (const float*)d_in[5];  // (1000)
    float* out = (float*)d_out;

    float* He = nullptr;
    float* Hd = nullptr;
    cudaGetSymbolAddress((void**)&He, g_He);
    cudaGetSymbolAddress((void**)&Hd, g_Hd);

    // He = enc @ W1[:, :512]^T              (1024 x 512)
    proj_kernel<<<dim3((B_DIM * T_DIM) / 64, K_DIM / 64), 256>>>(
        enc, W1, b1, He, 0, 0);
    // Hd = dec @ W1[:, 512:]^T + b1         (256 x 512)
    proj_kernel<<<dim3((B_DIM * U_DIM) / 64, K_DIM / 64), 256>>>(
        dec, W1, b1, Hd, D_DIM, 1);
    // out = tanh(He[t] + Hd[u]) @ W2^T + b2
    joint_kernel<<<dim3((V_DIM + BN - 1) / BN, M_TOTAL / BM), 256>>>(
        He, Hd, W2, b2, out);
}

// round 3
// speedup vs baseline: 3.5042x; 3.5042x over previous
#include <cuda_runtime.h>
#include <cstdint>

// Shapes (fixed): enc (4,256,512)  dec (4,64,512)  W1 (512,1024)  b1 (512)
// W2 (1000,512)  b2 (1000)  out (4,256,64,1000) fp32
#define B_DIM 4
#define T_DIM 256
#define U_DIM 64
#define D_DIM 512
#define K_DIM 512
#define V_DIM 1000
#define M_TOTAL (B_DIM * T_DIM * U_DIM)   // 65536
#define NKS    (K_DIM / 8)                 // 64 ksteps of k=8
#define MT_TOTAL (M_TOTAL / 16)            // 4096 m-tiles
#define NT_TOTAL 128                       // 1024 padded cols / 8

// ---------------- scratch (__device__ globals; allocation-free) -------------
__device__ float g_He[B_DIM * T_DIM * K_DIM];                 // 1024 x 512
__device__ float g_Hd[B_DIM * U_DIM * K_DIM];                 // 256 x 512 (b1 folded)
// H in mma-A-fragment order: [mtile][kstep][lane][4] as tf32 bit patterns.
__device__ unsigned int g_Hf[MT_TOTAL * NKS * 32 * 4 + 2048];
// W2 in mma-B-fragment order: [ntile][kstep][lane][2]
__device__ unsigned int g_W2f[NT_TOTAL * NKS * 32 * 2 + 2048];

// ---------------- helpers ---------------------------------------------------
__device__ __forceinline__ unsigned int f2tf32(float x) {
    unsigned int y;
    asm("cvt.rna.tf32.f32 %0, %1;" : "=r"(y) : "f"(x));
    return y;
}

__device__ __forceinline__ float fast_tanh(float x) {
    // tanh(x) = (e^{2x}-1)/(e^{2x}+1); ex2/rcp approx, clamped (tanh(10)=1-4e-9)
    x = fminf(fmaxf(x, -10.0f), 10.0f);
    float t;
    asm("ex2.approx.f32 %0, %1;" : "=f"(t) : "f"(x * 2.885390081777927f)); // 2*log2(e)
    float r;
    asm("rcp.approx.f32 %0, %1;" : "=f"(r) : "f"(t + 1.0f));
    return (t - 1.0f) * r;
}

__device__ __forceinline__ void mma_tf32(float* c,
                                         unsigned a0, unsigned a1, unsigned a2, unsigned a3,
                                         unsigned b0, unsigned b1)
{
    asm volatile(
        "mma.sync.aligned.m16n8k8.row.col.f32.tf32.tf32.f32 "
        "{%0,%1,%2,%3}, {%4,%5,%6,%7}, {%8,%9}, {%0,%1,%2,%3};\n"
        : "+f"(c[0]), "+f"(c[1]), "+f"(c[2]), "+f"(c[3])
        : "r"(a0), "r"(a1), "r"(a2), "r"(a3), "r"(b0), "r"(b1));
}

// ---------------- projections: He = enc@W1e^T ; Hd = dec@W1d^T + b1 ---------
// z=0: enc (1024 rows); z=1: dec (256 rows). Tiles 32x64, BK=16, 256 thr.
__global__ __launch_bounds__(256)
void proj_kernel(const float* __restrict__ enc, const float* __restrict__ dec,
                 const float* __restrict__ W1, const float* __restrict__ b1,
                 float* __restrict__ He, float* __restrict__ Hd)
{
    __shared__ float As[32][17];
    __shared__ float Bs[64][17];
    const int z = blockIdx.z;
    const int Mrows = z ? (B_DIM * U_DIM) : (B_DIM * T_DIM);
    const int m0 = blockIdx.x * 32;
    if (m0 >= Mrows) return;
    const float* X = z ? dec : enc;
    float* out = z ? Hd : He;
    const int dOff = z ? D_DIM : 0;
    const int n0 = blockIdx.y * 64;
    const int tid = threadIdx.x;
    const int tx = tid & 15;
    const int ty = tid >> 4;

    float acc[2][4];
#pragma unroll
    for (int i = 0; i < 2; i++)
#pragma unroll
        for (int j = 0; j < 4; j++) acc[i][j] = 0.0f;

    for (int k0 = 0; k0 < D_DIM; k0 += 16) {
#pragma unroll
        for (int i = 0; i < 2; i++) {
            int e = tid + i * 256;
            As[e >> 4][e & 15] = X[(m0 + (e >> 4)) * D_DIM + k0 + (e & 15)];
        }
#pragma unroll
        for (int i = 0; i < 4; i++) {
            int e = tid + i * 256;
            Bs[e >> 4][e & 15] = W1[(n0 + (e >> 4)) * (2 * D_DIM) + dOff + k0 + (e & 15)];
        }
        __syncthreads();
#pragma unroll
        for (int d = 0; d < 16; d++) {
            float a0 = As[ty * 2][d];
            float a1 = As[ty * 2 + 1][d];
#pragma unroll
            for (int j = 0; j < 4; j++) {
                float b = Bs[tx * 4 + j][d];
                acc[0][j] += a0 * b;
                acc[1][j] += a1 * b;
            }
        }
        __syncthreads();
    }

#pragma unroll
    for (int i = 0; i < 2; i++)
#pragma unroll
        for (int j = 0; j < 4; j++) {
            int n = n0 + tx * 4 + j;
            float v = acc[i][j];
            if (z) v += b1[n];
            out[(m0 + ty * 2 + i) * K_DIM + n] = v;
        }
}

// ---------------- H = tanh(He + Hd) into fragment-major tf32 ----------------
// One thread per (mtile, kstep, lane) -> 4 values -> one uint4 store.
__global__ __launch_bounds__(256)
void tanh_swizzle_kernel(const float* __restrict__ He, const float* __restrict__ Hd,
                         unsigned int* __restrict__ Hf)
{
    const int idx = blockIdx.x * 256 + threadIdx.x;       // < MT_TOTAL*NKS*32
    const int mt = idx >> 11;                              // / (64*32)
    const int rem = idx & 2047;
    const int ks = rem >> 5;
    const int lane = rem & 31;
    const int gp = lane >> 2;
    const int tg = lane & 3;
    const int c0 = ks * 8 + tg;

    const int r0 = mt * 16 + gp;
    const int r1 = r0 + 8;
    const float* he0 = He + (((r0 >> 14) << 8) + ((r0 >> 6) & 255)) * K_DIM;
    const float* hd0 = Hd + (((r0 >> 14) << 6) + (r0 & 63)) * K_DIM;
    const float* he1 = He + (((r1 >> 14) << 8) + ((r1 >> 6) & 255)) * K_DIM;
    const float* hd1 = Hd + (((r1 >> 14) << 6) + (r1 & 63)) * K_DIM;

    uint4 o;
    o.x = f2tf32(fast_tanh(he0[c0]     + hd0[c0]));      // (r0, c0)   -> a0
    o.y = f2tf32(fast_tanh(he1[c0]     + hd1[c0]));      // (r1, c0)   -> a1
    o.z = f2tf32(fast_tanh(he0[c0 + 4] + hd0[c0 + 4]));  // (r0, c0+4) -> a2
    o.w = f2tf32(fast_tanh(he1[c0 + 4] + hd1[c0 + 4]));  // (r1, c0+4) -> a3
    reinterpret_cast<uint4*>(Hf)[idx] = o;
}

// ---------------- W2 into fragment-major tf32 (zero-padded to 1024) ---------
__global__ __launch_bounds__(256)
void w2_swizzle_kernel(const float* __restrict__ W2, unsigned int* __restrict__ W2f)
{
    const int idx = blockIdx.x * 256 + threadIdx.x;       // < NT_TOTAL*NKS*32
    const int nt = idx >> 11;
    const int rem = idx & 2047;
    const int ks = rem >> 5;
    const int lane = rem & 31;
    const int gp = lane >> 2;
    const int tg = lane & 3;
    const int n = nt * 8 + gp;
    const int k = ks * 8 + tg;
    uint2 o;
    if (n < V_DIM) {
        o.x = f2tf32(W2[n * K_DIM + k]);
        o.y = f2tf32(W2[n * K_DIM + k + 4]);
    } else {
        o.x = 0u; o.y = 0u;
    }
    reinterpret_cast<uint2*>(W2f)[idx] = o;
}

// ---------------- GEMM: out = Hf @ W2f^T + b2 -------------------------------
// 128x128 block, 8 warps (2 along M x 4 along N), warp tile 64x32.
// No shared memory: operands pre-swizzled, direct LDG, double-buffered.
__global__ __launch_bounds__(256, 2)
void gemm_kernel(const unsigned int* __restrict__ Hf,
                 const unsigned int* __restrict__ W2f,
                 const float* __restrict__ b2,
                 float* __restrict__ out)
{
    const int tid = threadIdx.x;
    const int warp = tid >> 5;
    const int lane = tid & 31;
    const int wm = warp & 1;          // 2 warps along M
    const int wn = warp >> 1;         // 4 warps along N
    const int gp = lane >> 2;
    const int tg = lane & 3;

    const int mt0 = blockIdx.y * 8 + wm * 4;     // first global m-tile of warp
    const int nt0 = blockIdx.x * 16 + wn * 4;    // first global n-tile of warp

    // Base pointers (per-ks stride = 32 elements of uint4/uint2)
    const uint4* Ap = reinterpret_cast<const uint4*>(Hf)  + (size_t)mt0 * NKS * 32 + lane;
    const uint2* Bp = reinterpret_cast<const uint2*>(W2f) + (size_t)nt0 * NKS * 32 + lane;

    float acc[4][4][4];
#pragma unroll
    for (int mi = 0; mi < 4; mi++)
#pragma unroll
        for (int ni = 0; ni < 4; ni++)
#pragma unroll
            for (int q = 0; q < 4; q++) acc[mi][ni][q] = 0.0f;

    uint4 A0[4], A1[4];
    uint2 B0[4], B1[4];

#pragma unroll
    for (int mi = 0; mi < 4; mi++) A0[mi] = Ap[mi * (NKS * 32)];
#pragma unroll
    for (int ni = 0; ni < 4; ni++) B0[ni] = Bp[ni * (NKS * 32)];

#pragma unroll 4
    for (int ks = 0; ks < NKS; ks += 2) {
        // prefetch ks+1
#pragma unroll
        for (int mi = 0; mi < 4; mi++) A1[mi] = Ap[mi * (NKS * 32) + (ks + 1) * 32];
#pragma unroll
        for (int ni = 0; ni < 4; ni++) B1[ni] = Bp[ni * (NKS * 32) + (ks + 1) * 32];
        // mma ks (A0/B0)
#pragma unroll
        for (int mi = 0; mi < 4; mi++)
#pragma unroll
            for (int ni = 0; ni < 4; ni++)
                mma_tf32(acc[mi][ni], A0[mi].x, A0[mi].y, A0[mi].z, A0[mi].w,
                         B0[ni].x, B0[ni].y);
        // prefetch ks+2 (ks=62 -> reads pad region; harmless)
#pragma unroll
        for (int mi = 0; mi < 4; mi++) A0[mi] = Ap[mi * (NKS * 32) + (ks + 2) * 32];
#pragma unroll
        for (int ni = 0; ni < 4; ni++) B0[ni] = Bp[ni * (NKS * 32) + (ks + 2) * 32];
        // mma ks+1 (A1/B1)
#pragma unroll
        for (int mi = 0; mi < 4; mi++)
#pragma unroll
            for (int ni = 0; ni < 4; ni++)
                mma_tf32(acc[mi][ni], A1[mi].x, A1[mi].y, A1[mi].z, A1[mi].w,
                         B1[ni].x, B1[ni].y);
    }

    // Epilogue: + b2, write float2 pairs (cols even; V even)
    const int mbase = blockIdx.y * 128 + wm * 64;
    const int nbase = blockIdx.x * 128 + wn * 32;
#pragma unroll
    for (int mi = 0; mi < 4; mi++) {
        const int r0 = mbase + mi * 16 + gp;
#pragma unroll
        for (int ni = 0; ni < 4; ni++) {
            const int c = nbase + ni * 8 + tg * 2;
            if (c < V_DIM) {
                float bb0 = b2[c];
                float bb1 = b2[c + 1];
                float2 v0 = make_float2(acc[mi][ni][0] + bb0, acc[mi][ni][1] + bb1);
                float2 v1 = make_float2(acc[mi][ni][2] + bb0, acc[mi][ni][3] + bb1);
                *reinterpret_cast<float2*>(&out[(size_t)r0 * V_DIM + c]) = v0;
                *reinterpret_cast<float2*>(&out[(size_t)(r0 + 8) * V_DIM + c]) = v1;
            }
        }
    }
}

// ---------------------------------------------------------------------------
extern "C" void kernel_launch(void* const* d_in, const int* in_sizes, int n_in,
                              void* d_out, int out_size)
{
    const float* enc = (const float*)d_in[0];
    const float* dec = (const float*)d_in[1];
    const float* W1  = (const float*)d_in[2];
    const float* b1  = (const float*)d_in[3];
    const float* W2  = (const float*)d_in[4];
    const float* b2  = (const float*)d_in[5];
    float* out = (float*)d_out;

    float *He, *Hd;
    unsigned int *Hf, *W2f;
    cudaGetSymbolAddress((void**)&He, g_He);
    cudaGetSymbolAddress((void**)&Hd, g_Hd);
    cudaGetSymbolAddress((void**)&Hf, g_Hf);
    cudaGetSymbolAddress((void**)&W2f, g_W2f);

    // W2 fragment swizzle (independent)
    w2_swizzle_kernel<<<(NT_TOTAL * NKS * 32) / 256, 256>>>(W2, W2f);
    // Projections (z=0: He, z=1: Hd+b1)
    proj_kernel<<<dim3(32, K_DIM / 64, 2), 256>>>(enc, dec, W1, b1, He, Hd);
    // H = tanh(He+Hd) into fragment-major tf32
    tanh_swizzle_kernel<<<(MT_TOTAL * NKS * 32) / 256, 256>>>(He, Hd, Hf);
    // Big GEMM + bias
    gemm_kernel<<<dim3(8, M_TOTAL / 128), 256>>>(Hf, W2f, b2, out);
}

// round 9
// speedup vs baseline: 5.3900x; 1.5381x over previous
#include <cuda_runtime.h>
#include <cuda_fp16.h>
#include <cstdint>

// Shapes (fixed): enc (4,256,512)  dec (4,64,512)  W1 (512,1024)  b1 (512)
// W2 (1000,512)  b2 (1000)  out (4,256,64,1000) fp32
#define B_DIM 4
#define T_DIM 256
#define U_DIM 64
#define D_DIM 512
#define K_DIM 512
#define V_DIM 1000
#define M_TOTAL (B_DIM * T_DIM * U_DIM)   // 65536
#define NKS    (K_DIM / 16)                // 32 ksteps of k=16
#define MT_TOTAL (M_TOTAL / 16)            // 4096 m-tiles
#define NT_TOTAL 128                       // 1024 padded cols / 8

// ---------------- scratch (__device__ globals; allocation-free) -------------
__device__ float g_He[B_DIM * T_DIM * K_DIM];                 // 1024 x 512
__device__ float g_Hd[B_DIM * U_DIM * K_DIM];                 // 256 x 512 (b1 folded)
// H as fp16 mma-A fragments: [mtile][kstep][lane] -> uint4 (regs R0..R3)
__device__ unsigned int g_Hh[MT_TOTAL * NKS * 32 * 4 + 2048];
// W2 as fp16 mma-B fragments: [ntile][kstep][lane] -> uint2 (regs R0..R1)
__device__ unsigned int g_W2h[NT_TOTAL * NKS * 32 * 2 + 2048];

// ---------------- helpers ---------------------------------------------------
__device__ __forceinline__ float fast_tanh(float x) {
    x = fminf(fmaxf(x, -10.0f), 10.0f);
    float t, r;
    asm("ex2.approx.f32 %0, %1;" : "=f"(t) : "f"(x * 2.885390081777927f)); // 2*log2(e)
    asm("rcp.approx.f32 %0, %1;" : "=f"(r) : "f"(t + 1.0f));
    return (t - 1.0f) * r;
}

__device__ __forceinline__ unsigned int pack_h2(float a, float b) {
    __half2 h = __floats2half2_rn(a, b);
    return *reinterpret_cast<unsigned int*>(&h);
}

__device__ __forceinline__ void mma_f16(float* c,
                                        unsigned a0, unsigned a1, unsigned a2, unsigned a3,
                                        unsigned b0, unsigned b1)
{
    asm volatile(
        "mma.sync.aligned.m16n8k16.row.col.f32.f16.f16.f32 "
        "{%0,%1,%2,%3}, {%4,%5,%6,%7}, {%8,%9}, {%0,%1,%2,%3};\n"
        : "+f"(c[0]), "+f"(c[1]), "+f"(c[2]), "+f"(c[3])
        : "r"(a0), "r"(a1), "r"(a2), "r"(a3), "r"(b0), "r"(b1));
}

// ---------------- projections: He = enc@W1e^T ; Hd = dec@W1d^T + b1 ---------
__global__ __launch_bounds__(256)
void proj_kernel(const float* __restrict__ enc, const float* __restrict__ dec,
                 const float* __restrict__ W1, const float* __restrict__ b1,
                 float* __restrict__ He, float* __restrict__ Hd)
{
    __shared__ float As[32][17];
    __shared__ float Bs[64][17];
    const int z = blockIdx.z;
    const int Mrows = z ? (B_DIM * U_DIM) : (B_DIM * T_DIM);
    const int m0 = blockIdx.x * 32;
    if (m0 >= Mrows) return;
    const float* X = z ? dec : enc;
    float* out = z ? Hd : He;
    const int dOff = z ? D_DIM : 0;
    const int n0 = blockIdx.y * 64;
    const int tid = threadIdx.x;
    const int tx = tid & 15;
    const int ty = tid >> 4;

    float acc[2][4];
#pragma unroll
    for (int i = 0; i < 2; i++)
#pragma unroll
        for (int j = 0; j < 4; j++) acc[i][j] = 0.0f;

    for (int k0 = 0; k0 < D_DIM; k0 += 16) {
#pragma unroll
        for (int i = 0; i < 2; i++) {
            int e = tid + i * 256;
            As[e >> 4][e & 15] = X[(m0 + (e >> 4)) * D_DIM + k0 + (e & 15)];
        }
#pragma unroll
        for (int i = 0; i < 4; i++) {
            int e = tid + i * 256;
            Bs[e >> 4][e & 15] = W1[(n0 + (e >> 4)) * (2 * D_DIM) + dOff + k0 + (e & 15)];
        }
        __syncthreads();
#pragma unroll
        for (int d = 0; d < 16; d++) {
            float a0 = As[ty * 2][d];
            float a1 = As[ty * 2 + 1][d];
#pragma unroll
            for (int j = 0; j < 4; j++) {
                float b = Bs[tx * 4 + j][d];
                acc[0][j] += a0 * b;
                acc[1][j] += a1 * b;
            }
        }
        __syncthreads();
    }
#pragma unroll
    for (int i = 0; i < 2; i++)
#pragma unroll
        for (int j = 0; j < 4; j++) {
            int n = n0 + tx * 4 + j;
            float v = acc[i][j];
            if (z) v += b1[n];
            out[(m0 + ty * 2 + i) * K_DIM + n] = v;
        }
}

// ---------------- H = tanh(He + Hd) into fp16 A-fragment order --------------
// m16n8k16 A layout per lane (gp=lane>>2, tg=lane&3), kstep base kb=ks*16:
//  R0: (r0, kb+2tg, +1)  R1: (r1, kb+2tg, +1)  R2: (r0, kb+2tg+8, +1)  R3: (r1, ...)
__global__ __launch_bounds__(256)
void tanh_swizzle_kernel(const float* __restrict__ He, const float* __restrict__ Hd,
                         unsigned int* __restrict__ Hh)
{
    const int idx = blockIdx.x * 256 + threadIdx.x;       // < MT_TOTAL*NKS*32
    const int mt = idx >> 10;                              // / (32*32)
    const int rem = idx & 1023;
    const int ks = rem >> 5;
    const int lane = rem & 31;
    const int gp = lane >> 2;
    const int tg = lane & 3;
    const int c0 = ks * 16 + tg * 2;

    const int r0 = mt * 16 + gp;
    const int r1 = r0 + 8;
    const float* he0 = He + (((r0 >> 14) << 8) + ((r0 >> 6) & 255)) * K_DIM;
    const float* hd0 = Hd + (((r0 >> 14) << 6) + (r0 & 63)) * K_DIM;
    const float* he1 = He + (((r1 >> 14) << 8) + ((r1 >> 6) & 255)) * K_DIM;
    const float* hd1 = Hd + (((r1 >> 14) << 6) + (r1 & 63)) * K_DIM;

    float2 e0a = *reinterpret_cast<const float2*>(he0 + c0);
    float2 d0a = *reinterpret_cast<const float2*>(hd0 + c0);
    float2 e1a = *reinterpret_cast<const float2*>(he1 + c0);
    float2 d1a = *reinterpret_cast<const float2*>(hd1 + c0);
    float2 e0b = *reinterpret_cast<const float2*>(he0 + c0 + 8);
    float2 d0b = *reinterpret_cast<const float2*>(hd0 + c0 + 8);
    float2 e1b = *reinterpret_cast<const float2*>(he1 + c0 + 8);
    float2 d1b = *reinterpret_cast<const float2*>(hd1 + c0 + 8);

    uint4 o;
    o.x = pack_h2(fast_tanh(e0a.x + d0a.x), fast_tanh(e0a.y + d0a.y));
    o.y = pack_h2(fast_tanh(e1a.x + d1a.x), fast_tanh(e1a.y + d1a.y));
    o.z = pack_h2(fast_tanh(e0b.x + d0b.x), fast_tanh(e0b.y + d0b.y));
    o.w = pack_h2(fast_tanh(e1b.x + d1b.x), fast_tanh(e1b.y + d1b.y));
    reinterpret_cast<uint4*>(Hh)[idx] = o;
}

// ---------------- W2 into fp16 B-fragment order (zero-padded to 1024) -------
// B layout per lane: R0: (kb+2tg, +1; n=nt*8+gp)  R1: (kb+2tg+8, +1; same n)
__global__ __launch_bounds__(256)
void w2_swizzle_kernel(const float* __restrict__ W2, unsigned int* __restrict__ W2h)
{
    const int idx = blockIdx.x * 256 + threadIdx.x;       // < NT_TOTAL*NKS*32
    const int nt = idx >> 10;
    const int rem = idx & 1023;
    const int ks = rem >> 5;
    const int lane = rem & 31;
    const int gp = lane >> 2;
    const int tg = lane & 3;
    const int n = nt * 8 + gp;
    const int k = ks * 16 + tg * 2;
    uint2 o = make_uint2(0u, 0u);
    if (n < V_DIM) {
        float2 wa = *reinterpret_cast<const float2*>(W2 + n * K_DIM + k);
        float2 wb = *reinterpret_cast<const float2*>(W2 + n * K_DIM + k + 8);
        o.x = pack_h2(wa.x, wa.y);
        o.y = pack_h2(wb.x, wb.y);
    }
    reinterpret_cast<uint2*>(W2h)[idx] = o;
}

// ---------------- GEMM: out = Hh @ W2h^T + b2 (fp16 mma, fp32 accum) --------
// 128x128 block, 8 warps (2 along M x 4 along N), warp tile 64x32.
// No shared memory: operands pre-swizzled, direct LDG, double-buffered.
__global__ __launch_bounds__(256, 2)
void gemm_kernel(const unsigned int* __restrict__ Hh,
                 const unsigned int* __restrict__ W2h,
                 const float* __restrict__ b2,
                 float* __restrict__ out)
{
    const int tid = threadIdx.x;
    const int warp = tid >> 5;
    const int lane = tid & 31;
    const int wm = warp & 1;          // 2 warps along M
    const int wn = warp >> 1;         // 4 warps along N
    const int gp = lane >> 2;
    const int tg = lane & 3;

    const int mt0 = blockIdx.y * 8 + wm * 4;
    const int nt0 = blockIdx.x * 16 + wn * 4;

    const uint4* Ap = reinterpret_cast<const uint4*>(Hh)  + (size_t)mt0 * NKS * 32 + lane;
    const uint2* Bp = reinterpret_cast<const uint2*>(W2h) + (size_t)nt0 * NKS * 32 + lane;

    float acc[4][4][4];
#pragma unroll
    for (int mi = 0; mi < 4; mi++)
#pragma unroll
        for (int ni = 0; ni < 4; ni++)
#pragma unroll
            for (int q = 0; q < 4; q++) acc[mi][ni][q] = 0.0f;

    uint4 A0[4], A1[4];
    uint2 B0[4], B1[4];

#pragma unroll
    for (int mi = 0; mi < 4; mi++) A0[mi] = Ap[mi * (NKS * 32)];
#pragma unroll
    for (int ni = 0; ni < 4; ni++) B0[ni] = Bp[ni * (NKS * 32)];

#pragma unroll 4
    for (int ks = 0; ks < NKS; ks += 2) {
        // prefetch ks+1
#pragma unroll
        for (int mi = 0; mi < 4; mi++) A1[mi] = Ap[mi * (NKS * 32) + (ks + 1) * 32];
#pragma unroll
        for (int ni = 0; ni < 4; ni++) B1[ni] = Bp[ni * (NKS * 32) + (ks + 1) * 32];
        // mma ks
#pragma unroll
        for (int mi = 0; mi < 4; mi++)
#pragma unroll
            for (int ni = 0; ni < 4; ni++)
                mma_f16(acc[mi][ni], A0[mi].x, A0[mi].y, A0[mi].z, A0[mi].w,
                        B0[ni].x, B0[ni].y);
        // prefetch ks+2 (last reads pad region; harmless)
#pragma unroll
        for (int mi = 0; mi < 4; mi++) A0[mi] = Ap[mi * (NKS * 32) + (ks + 2) * 32];
#pragma unroll
        for (int ni = 0; ni < 4; ni++) B0[ni] = Bp[ni * (NKS * 32) + (ks + 2) * 32];
        // mma ks+1
#pragma unroll
        for (int mi = 0; mi < 4; mi++)
#pragma unroll
            for (int ni = 0; ni < 4; ni++)
                mma_f16(acc[mi][ni], A1[mi].x, A1[mi].y, A1[mi].z, A1[mi].w,
                        B1[ni].x, B1[ni].y);
    }

    // Epilogue: + b2, write float2 pairs (cols even; V even)
    const int mbase = blockIdx.y * 128 + wm * 64;
    const int nbase = blockIdx.x * 128 + wn * 32;
#pragma unroll
    for (int mi = 0; mi < 4; mi++) {
        const int r0 = mbase + mi * 16 + gp;
#pragma unroll
        for (int ni = 0; ni < 4; ni++) {
            const int c = nbase + ni * 8 + tg * 2;
            if (c < V_DIM) {
                float bb0 = b2[c];
                float bb1 = b2[c + 1];
                float2 v0 = make_float2(acc[mi][ni][0] + bb0, acc[mi][ni][1] + bb1);
                float2 v1 = make_float2(acc[mi][ni][2] + bb0, acc[mi][ni][3] + bb1);
                *reinterpret_cast<float2*>(&out[(size_t)r0 * V_DIM + c]) = v0;
                *reinterpret_cast<float2*>(&out[(size_t)(r0 + 8) * V_DIM + c]) = v1;
            }
        }
    }
}

// ---------------------------------------------------------------------------
extern "C" void kernel_launch(void* const* d_in, const int* in_sizes, int n_in,
                              void* d_out, int out_size)
{
    const float* enc = (const float*)d_in[0];
    const float* dec = (const float*)d_in[1];
    const float* W1  = (const float*)d_in[2];
    const float* b1  = (const float*)d_in[3];
    const float* W2  = (const float*)d_in[4];
    const float* b2  = (const float*)d_in[5];
    float* out = (float*)d_out;

    float *He, *Hd;
    unsigned int *Hh, *W2h;
    cudaGetSymbolAddress((void**)&He, g_He);
    cudaGetSymbolAddress((void**)&Hd, g_Hd);
    cudaGetSymbolAddress((void**)&Hh, g_Hh);
    cudaGetSymbolAddress((void**)&W2h, g_W2h);

    w2_swizzle_kernel<<<(NT_TOTAL * NKS * 32) / 256, 256>>>(W2, W2h);
    proj_kernel<<<dim3(32, K_DIM / 64, 2), 256>>>(enc, dec, W1, b1, He, Hd);
    tanh_swizzle_kernel<<<(MT_TOTAL * NKS * 32) / 256, 256>>>(He, Hd, Hh);
    gemm_kernel<<<dim3(8, M_TOTAL / 128), 256>>>(Hh, W2h, b2, out);
}